// round 3
// baseline (speedup 1.0000x reference)
#include <cuda_runtime.h>
#include <math.h>
#include <stdint.h>

#define B_ 4
#define T_ 2048
#define D_ 512
#define M_ (B_*T_)   /* 8192 */

/* ------------ static device scratch (no allocations) ------------ */
__device__ float g_xpe[(size_t)M_*D_];          // x + PE
__device__ float g_xp [(size_t)4*M_*3*D_];      // wih @ xpe + bih
__device__ float g_q  [(size_t)4*M_*D_];
__device__ float g_kk [(size_t)4*M_*D_];
__device__ float g_v  [(size_t)4*M_*D_];
__device__ float g_comb[(size_t)4*M_*2*D_];     // [gru | attn]
__device__ float g_thr[(size_t)4*M_*D_];        // beat -> thr (in place)
__device__ float g_mix[(size_t)M_*D_];
__device__ float g_h[3*4*4*512];                // triple-buffered hidden
__device__ int   g_flags[128];

/* ---------------------------- init ------------------------------ */
__global__ void init_kernel() {
    int i = blockIdx.x * 256 + threadIdx.x;
    if (i < 4*4*512) g_h[i] = 0.0f;
    if (i < 128)     g_flags[i] = 0;
}

/* -------------------- positional encoding ----------------------- */
__global__ void pe_add_kernel(const float* __restrict__ x) {
    int idx = blockIdx.x * 256 + threadIdx.x;   // 0 .. T*D-1
    int t = idx >> 9;
    int d = idx & 511;
    const float kfac = -9.210340371976184f / 512.0f;
    float dv  = expf((float)(d & ~1) * kfac);
    float arg = (float)t * dv;
    float pe  = (d & 1) ? cosf(arg) : sinf(arg);
    int slot = d >> 7;
    int off  = d & 127;
    int c    = 5 + slot;
    float ph = ((float)(t % c) / (float)c) * 6.283185307179586f;
    float tv = (off < 64) ? sinf(ph * (float)(off + 1)) : cosf(ph * (float)(off - 63));
    float tot = 0.5f * pe + 0.5f * tv;
    #pragma unroll
    for (int b = 0; b < B_; ++b)
        g_xpe[(size_t)b*(T_*D_) + idx] = x[(size_t)b*(T_*D_) + idx] + tot;
}

/* --------------------- generic NT SGEMM -------------------------
   C[z,m,n] = sum_j A(z,m,j) * W[z*sWz + n*K + j] (+ bias[z,n])
   A addr = z*sAz + m*sAm + (j>>9)*sAchunk + (j&511)                */
__global__ void __launch_bounds__(256)
gemm_kernel(const float* __restrict__ A, size_t sAz, size_t sAm, size_t sAchunk,
            const float* __restrict__ W, size_t sWz, int K,
            const float* __restrict__ bias, size_t sBz,
            float* __restrict__ C, size_t sCz, size_t sCm)
{
    __shared__ float As[16][132];
    __shared__ float Bs[16][132];
    const int z  = blockIdx.z;
    const int m0 = blockIdx.x * 128;
    const int n0 = blockIdx.y * 128;
    const int tid = threadIdx.x;
    const int lr = tid >> 1;
    const int lc = (tid & 1) * 8;
    const int tx = tid & 15, ty = tid >> 4;

    const float* Az = A + (size_t)z * sAz;
    const float* Wz = W + (size_t)z * sWz;
    float acc[8][8];
    #pragma unroll
    for (int i = 0; i < 8; ++i)
        #pragma unroll
        for (int j = 0; j < 8; ++j) acc[i][j] = 0.f;

    for (int j0 = 0; j0 < K; j0 += 16) {
        const float* ap = Az + (size_t)(m0 + lr) * sAm + (size_t)(j0 >> 9) * sAchunk + (j0 & 511) + lc;
        float4 a0 = *(const float4*)(ap);
        float4 a1 = *(const float4*)(ap + 4);
        const float* wp = Wz + (size_t)(n0 + lr) * K + j0 + lc;
        float4 b0 = *(const float4*)(wp);
        float4 b1 = *(const float4*)(wp + 4);
        As[lc+0][lr]=a0.x; As[lc+1][lr]=a0.y; As[lc+2][lr]=a0.z; As[lc+3][lr]=a0.w;
        As[lc+4][lr]=a1.x; As[lc+5][lr]=a1.y; As[lc+6][lr]=a1.z; As[lc+7][lr]=a1.w;
        Bs[lc+0][lr]=b0.x; Bs[lc+1][lr]=b0.y; Bs[lc+2][lr]=b0.z; Bs[lc+3][lr]=b0.w;
        Bs[lc+4][lr]=b1.x; Bs[lc+5][lr]=b1.y; Bs[lc+6][lr]=b1.z; Bs[lc+7][lr]=b1.w;
        __syncthreads();
        #pragma unroll
        for (int kk = 0; kk < 16; ++kk) {
            float af[8], bf[8];
            *(float4*)&af[0] = *(const float4*)&As[kk][ty*8];
            *(float4*)&af[4] = *(const float4*)&As[kk][ty*8+4];
            *(float4*)&bf[0] = *(const float4*)&Bs[kk][tx*8];
            *(float4*)&bf[4] = *(const float4*)&Bs[kk][tx*8+4];
            #pragma unroll
            for (int i = 0; i < 8; ++i)
                #pragma unroll
                for (int j = 0; j < 8; ++j)
                    acc[i][j] += af[i] * bf[j];
        }
        __syncthreads();
    }

    float bv[8];
    if (bias) {
        #pragma unroll
        for (int j = 0; j < 8; ++j) bv[j] = bias[(size_t)z*sBz + n0 + tx*8 + j];
    } else {
        #pragma unroll
        for (int j = 0; j < 8; ++j) bv[j] = 0.f;
    }
    float* Cz = C + (size_t)z * sCz;
    #pragma unroll
    for (int i = 0; i < 8; ++i) {
        float* cp = Cz + (size_t)(m0 + ty*8 + i) * sCm + n0 + tx*8;
        float4 o0 = make_float4(acc[i][0]+bv[0], acc[i][1]+bv[1], acc[i][2]+bv[2], acc[i][3]+bv[3]);
        float4 o1 = make_float4(acc[i][4]+bv[4], acc[i][5]+bv[5], acc[i][6]+bv[6], acc[i][7]+bv[7]);
        *(float4*)cp     = o0;
        *(float4*)(cp+4) = o1;
    }
}

/* --------------------------- GRU --------------------------------
   grid = 128 CTAs: blockIdx = k*32 + c. CTA owns hidden units
   c*16..c*16+15 for thread k, whh slice (48 rows x 512) in SMEM.  */
__global__ void __launch_bounds__(256, 1)
gru_kernel(const float* __restrict__ whh, const float* __restrict__ bhh)
{
    extern __shared__ float sm[];
    float* sW    = sm;            // 48*512 = 24576
    float* sGh   = sm + 24576;    // [48][4] = 192
    float* sBhh  = sGh + 192;     // 48
    float* sHold = sBhh + 48;     // [16][4] = 64

    const int tid  = threadIdx.x;
    const int kt   = blockIdx.x >> 5;
    const int c    = blockIdx.x & 31;
    const int lane = tid & 31;
    const int w    = tid >> 5;
    const int jbase = 4 * lane;

    // load weight slice: rows g*512 + c*16 + u  (g=0..2, u=0..15)
    const float* wkp = whh + (size_t)kt * (1536*512);
    for (int i = tid; i < 48*128; i += 256) {
        int row = i >> 7;              // 0..47
        int j   = (i & 127) * 4;
        int g = row >> 4, u = row & 15;
        float4 v = *(const float4*)(wkp + (size_t)(g*512 + c*16 + u)*512 + j);
        *(float4*)(sW + row*512 + j) = v;
    }
    if (tid < 48) {
        int g = tid >> 4, u = tid & 15;
        sBhh[tid] = bhh[kt*1536 + g*512 + c*16 + u];
    }
    if (tid < 64) sHold[tid] = 0.f;
    __syncthreads();

    volatile int* flags = (volatile int*)(g_flags + kt*32);
    const int u  = tid >> 2;
    const int b4 = tid & 3;

    for (int t = 0; t < T_; ++t) {
        // prefetch this step's xp gate inputs (independent of flag sync)
        float xr = 0.f, xz = 0.f, xn = 0.f;
        if (tid < 64) {
            const float* xp = g_xp + ((size_t)(kt*M_ + b4*T_ + t))*1536 + c*16 + u;
            xr = __ldg(xp); xz = __ldg(xp + 512); xn = __ldg(xp + 1024);
        }
        // wait for previous step's h from all 32 CTAs of this k
        if (t > 0) {
            if (tid < 32) { while (flags[tid] < t) { } }
            __syncthreads();
            __threadfence();
        }
        // gather full h into registers (lane owns j = 4*lane + 128e + 0..3)
        const float* hb = g_h + (size_t)(t % 3) * (4*4*512) + (size_t)kt * (4*512);
        float4 hreg[4][4];
        #pragma unroll
        for (int b = 0; b < 4; ++b)
            #pragma unroll
            for (int e = 0; e < 4; ++e)
                hreg[b][e] = *(const float4*)(hb + b*512 + jbase + 128*e);

        // matvec: warp w -> rows w*6 .. w*6+5
        #pragma unroll
        for (int i = 0; i < 6; ++i) {
            int row = w*6 + i;
            float a0 = 0.f, a1 = 0.f, a2 = 0.f, a3 = 0.f;
            #pragma unroll
            for (int e = 0; e < 4; ++e) {
                float4 wv = *(const float4*)(sW + row*512 + jbase + 128*e);
                a0 += wv.x*hreg[0][e].x + wv.y*hreg[0][e].y + wv.z*hreg[0][e].z + wv.w*hreg[0][e].w;
                a1 += wv.x*hreg[1][e].x + wv.y*hreg[1][e].y + wv.z*hreg[1][e].z + wv.w*hreg[1][e].w;
                a2 += wv.x*hreg[2][e].x + wv.y*hreg[2][e].y + wv.z*hreg[2][e].z + wv.w*hreg[2][e].w;
                a3 += wv.x*hreg[3][e].x + wv.y*hreg[3][e].y + wv.z*hreg[3][e].z + wv.w*hreg[3][e].w;
            }
            #pragma unroll
            for (int off = 16; off; off >>= 1) {
                a0 += __shfl_xor_sync(0xffffffffu, a0, off);
                a1 += __shfl_xor_sync(0xffffffffu, a1, off);
                a2 += __shfl_xor_sync(0xffffffffu, a2, off);
                a3 += __shfl_xor_sync(0xffffffffu, a3, off);
            }
            if (lane == 0) {
                sGh[row*4 + 0] = a0; sGh[row*4 + 1] = a1;
                sGh[row*4 + 2] = a2; sGh[row*4 + 3] = a3;
            }
        }
        __syncthreads();

        // gates + state update (64 threads: u x b4)
        if (tid < 64) {
            float hr = sGh[(u)*4      + b4] + sBhh[u];
            float hz = sGh[(16+u)*4   + b4] + sBhh[16+u];
            float hn = sGh[(32+u)*4   + b4] + sBhh[32+u];
            float r = 1.f / (1.f + expf(-(xr + hr)));
            float z = 1.f / (1.f + expf(-(xz + hz)));
            float n = tanhf(xn + r * hn);
            float hold = sHold[tid];
            float hnew = (1.f - z) * n + z * hold;
            sHold[tid] = hnew;
            g_h[(size_t)((t+1) % 3) * (4*4*512) + (size_t)kt * (4*512) + b4*512 + c*16 + u] = hnew;
            g_comb[((size_t)(kt*M_ + b4*T_ + t)) * 1024 + c*16 + u] = hnew;
            __threadfence();
        }
        __syncthreads();
        if (tid == 0) { __threadfence(); flags[c] = t + 1; }
    }
}

/* ------------------------- attention ---------------------------- */
__global__ void attn_kernel() {
    int gw   = blockIdx.x * 8 + (threadIdx.x >> 5);   // (k*4+b)*2048 + t
    int lane = threadIdx.x & 31;
    int t  = gw & (T_ - 1);
    int kb = gw >> 11;
    int b  = kb & 3;
    int kt = kb >> 2;
    int c  = 5 + kt;
    int L  = min(c, t + 1);
    size_t rowbase = (size_t)kt * M_ + (size_t)b * T_;
    const float* qp = g_q + (rowbase + t) * D_;
    float4 qv[4];
    #pragma unroll
    for (int e = 0; e < 4; ++e) qv[e] = *(const float4*)(qp + 4*lane + 128*e);

    float sc[8];
    float smax = -1e30f;
    #pragma unroll
    for (int s0 = 0; s0 < 8; ++s0) {
        if (s0 < L) {
            const float* kp = g_kk + (rowbase + t - s0) * D_;
            float a = 0.f;
            #pragma unroll
            for (int e = 0; e < 4; ++e) {
                float4 kv = *(const float4*)(kp + 4*lane + 128*e);
                a += qv[e].x*kv.x + qv[e].y*kv.y + qv[e].z*kv.z + qv[e].w*kv.w;
            }
            #pragma unroll
            for (int off = 16; off; off >>= 1) a += __shfl_xor_sync(0xffffffffu, a, off);
            a *= 0.044194173824159216f;   // 1/sqrt(512)
            sc[s0] = a;
            smax = fmaxf(smax, a);
        }
    }
    float denom = 0.f;
    float4 acc[4];
    #pragma unroll
    for (int e = 0; e < 4; ++e) acc[e] = make_float4(0.f, 0.f, 0.f, 0.f);
    #pragma unroll
    for (int s0 = 0; s0 < 8; ++s0) {
        if (s0 < L) {
            float p = expf(sc[s0] - smax);
            denom += p;
            const float* vp = g_v + (rowbase + t - s0) * D_;
            #pragma unroll
            for (int e = 0; e < 4; ++e) {
                float4 vv = *(const float4*)(vp + 4*lane + 128*e);
                acc[e].x += p*vv.x; acc[e].y += p*vv.y;
                acc[e].z += p*vv.z; acc[e].w += p*vv.w;
            }
        }
    }
    float inv = 1.f / denom;
    float* op = g_comb + (rowbase + t) * 1024 + 512;
    #pragma unroll
    for (int e = 0; e < 4; ++e) {
        float4 o = make_float4(acc[e].x*inv, acc[e].y*inv, acc[e].z*inv, acc[e].w*inv);
        *(float4*)(op + 4*lane + 128*e) = o;
    }
}

/* ----------------- layernorm (+residual) ------------------------ */
__global__ void ln_kernel(const float* __restrict__ inp, const float* __restrict__ res,
                          const float* __restrict__ gg, const float* __restrict__ bb,
                          float* __restrict__ out, int zdiv)
{
    int row  = blockIdx.x * 8 + (threadIdx.x >> 5);
    int lane = threadIdx.x & 31;
    int z    = zdiv ? (row / zdiv) : 0;
    int rrow = zdiv ? (row % zdiv) : row;
    const float* ip = inp + (size_t)row * 512;
    const float* rp = res + (size_t)rrow * 512;
    float4 v[4];
    float s = 0.f;
    #pragma unroll
    for (int e = 0; e < 4; ++e) {
        float4 a  = *(const float4*)(ip + 4*lane + 128*e);
        float4 r4 = *(const float4*)(rp + 4*lane + 128*e);
        v[e] = make_float4(a.x+r4.x, a.y+r4.y, a.z+r4.z, a.w+r4.w);
        s += v[e].x + v[e].y + v[e].z + v[e].w;
    }
    #pragma unroll
    for (int off = 16; off; off >>= 1) s += __shfl_xor_sync(0xffffffffu, s, off);
    float mean = s * (1.f/512.f);
    float q = 0.f;
    #pragma unroll
    for (int e = 0; e < 4; ++e) {
        float dx = v[e].x-mean, dy = v[e].y-mean, dz = v[e].z-mean, dw = v[e].w-mean;
        q += dx*dx + dy*dy + dz*dz + dw*dw;
    }
    #pragma unroll
    for (int off = 16; off; off >>= 1) q += __shfl_xor_sync(0xffffffffu, q, off);
    float rstd = rsqrtf(q * (1.f/512.f) + 1e-5f);
    const float* gp = gg + (size_t)z*512;
    const float* bp = bb + (size_t)z*512;
    #pragma unroll
    for (int e = 0; e < 4; ++e) {
        float4 g4 = *(const float4*)(gp + 4*lane + 128*e);
        float4 b4 = *(const float4*)(bp + 4*lane + 128*e);
        float4 o;
        o.x = (v[e].x-mean)*rstd*g4.x + b4.x;
        o.y = (v[e].y-mean)*rstd*g4.y + b4.y;
        o.z = (v[e].z-mean)*rstd*g4.z + b4.z;
        o.w = (v[e].w-mean)*rstd*g4.w + b4.w;
        *(float4*)(out + (size_t)row*512 + 4*lane + 128*e) = o;
    }
}

/* --------------------------- launch ------------------------------ */
extern "C" void kernel_launch(void* const* d_in, const int* in_sizes, int n_in,
                              void* d_out, int out_size)
{
    const float* x     = (const float*)d_in[0];
    const float* wih   = (const float*)d_in[1];
    const float* whh   = (const float*)d_in[2];
    const float* bih   = (const float*)d_in[3];
    const float* bhh   = (const float*)d_in[4];
    const float* wq    = (const float*)d_in[5];
    const float* wk    = (const float*)d_in[6];
    const float* wv    = (const float*)d_in[7];
    const float* wbeat = (const float*)d_in[8];
    const float* ng    = (const float*)d_in[9];
    const float* nb    = (const float*)d_in[10];
    const float* wmix  = (const float*)d_in[11];
    const float* bng   = (const float*)d_in[12];
    const float* bnb   = (const float*)d_in[13];
    float* out = (float*)d_out;

    float *p_xpe, *p_xp, *p_q, *p_k, *p_v, *p_comb, *p_thr, *p_mix;
    cudaGetSymbolAddress((void**)&p_xpe,  g_xpe);
    cudaGetSymbolAddress((void**)&p_xp,   g_xp);
    cudaGetSymbolAddress((void**)&p_q,    g_q);
    cudaGetSymbolAddress((void**)&p_k,    g_kk);
    cudaGetSymbolAddress((void**)&p_v,    g_v);
    cudaGetSymbolAddress((void**)&p_comb, g_comb);
    cudaGetSymbolAddress((void**)&p_thr,  g_thr);
    cudaGetSymbolAddress((void**)&p_mix,  g_mix);

    cudaFuncSetAttribute(gru_kernel, cudaFuncAttributeMaxDynamicSharedMemorySize, 100*1024);

    init_kernel<<<33, 256>>>();
    pe_add_kernel<<<(T_*D_)/256, 256>>>(x);

    // xp = wih @ xpe + bih   (M=8192, N=1536, K=512, z=4)
    gemm_kernel<<<dim3(64,12,4), 256>>>(p_xpe, 0, 512, 512,
                                        wih, (size_t)1536*512, 512,
                                        bih, 1536,
                                        p_xp, (size_t)M_*1536, 1536);
    // q, k, v  (N=512, K=512, z=4)
    gemm_kernel<<<dim3(64,4,4), 256>>>(p_xpe, 0, 512, 512, wq, (size_t)512*512, 512,
                                       nullptr, 0, p_q, (size_t)M_*512, 512);
    gemm_kernel<<<dim3(64,4,4), 256>>>(p_xpe, 0, 512, 512, wk, (size_t)512*512, 512,
                                       nullptr, 0, p_k, (size_t)M_*512, 512);
    gemm_kernel<<<dim3(64,4,4), 256>>>(p_xpe, 0, 512, 512, wv, (size_t)512*512, 512,
                                       nullptr, 0, p_v, (size_t)M_*512, 512);

    gru_kernel<<<128, 256, 99520>>>(whh, bhh);
    attn_kernel<<<4096, 256>>>();

    // beat = w_beat @ comb   (K=1024) -> g_thr
    gemm_kernel<<<dim3(64,4,4), 256>>>(p_comb, (size_t)M_*1024, 1024, 512,
                                       wbeat, (size_t)512*1024, 1024,
                                       nullptr, 0, p_thr, (size_t)M_*512, 512);
    // thr = LN(beat + xpe)   in place
    ln_kernel<<<4096, 256>>>(p_thr, p_xpe, ng, nb, p_thr, 8192);
    // out0 = w_mix @ merged  (K=2048 over the 4 thr chunks)
    gemm_kernel<<<dim3(64,4,1), 256>>>(p_thr, 0, 512, (size_t)M_*512,
                                       wmix, 0, 2048,
                                       nullptr, 0, p_mix, 0, 512);
    // out = LN(out0 + xpe)
    ln_kernel<<<1024, 256>>>(p_mix, p_xpe, bng, bnb, out, 0);
}